// round 1
// baseline (speedup 1.0000x reference)
#include <cuda_runtime.h>
#include <cuda_bf16.h>
#include <math.h>

// Problem constants
#define B_   2
#define T_   2048
#define C_   768
#define H_   12
#define DH_  64

#define BM 64
#define BN 64
#define BKK 16

// Scratch (device globals — no allocation allowed)
__device__ float g_q[B_ * T_ * C_];
__device__ float g_k[B_ * T_ * C_];
__device__ float g_v[B_ * T_ * C_];
__device__ float g_att[B_ * T_ * C_];

// ---------------------------------------------------------------------------
// Generic NT GEMM: C[m,n] = alpha * sum_k A[m*lda+k] * B[n*ldb+k]
// Requires M%64==0, N%64==0, K%16==0, 16B-aligned rows.
// ---------------------------------------------------------------------------
__global__ void gemm_nt_kernel(const float* __restrict__ A,
                               const float* __restrict__ Bm,
                               float* __restrict__ C,
                               int K, int lda, int ldb, int ldc, float alpha) {
    __shared__ float As[BKK][BM];
    __shared__ float Bs[BKK][BN];
    const int tid = threadIdx.x;
    const int tx = tid % 16, ty = tid / 16;
    const int m0 = blockIdx.y * BM, n0 = blockIdx.x * BN;

    float acc[4][4] = {};

    const int e = tid * 4;
    const int r = e / BKK, kko = e % BKK;

    for (int k0 = 0; k0 < K; k0 += BKK) {
        float4 va = *(const float4*)&A[(size_t)(m0 + r) * lda + k0 + kko];
        float4 vb = *(const float4*)&Bm[(size_t)(n0 + r) * ldb + k0 + kko];
        As[kko + 0][r] = va.x; As[kko + 1][r] = va.y;
        As[kko + 2][r] = va.z; As[kko + 3][r] = va.w;
        Bs[kko + 0][r] = vb.x; Bs[kko + 1][r] = vb.y;
        Bs[kko + 2][r] = vb.z; Bs[kko + 3][r] = vb.w;
        __syncthreads();
#pragma unroll
        for (int kk = 0; kk < BKK; kk++) {
            float a[4], b[4];
            float4 af = *(const float4*)&As[kk][ty * 4];
            float4 bf = *(const float4*)&Bs[kk][tx * 4];
            a[0] = af.x; a[1] = af.y; a[2] = af.z; a[3] = af.w;
            b[0] = bf.x; b[1] = bf.y; b[2] = bf.z; b[3] = bf.w;
#pragma unroll
            for (int i = 0; i < 4; i++)
#pragma unroll
                for (int j = 0; j < 4; j++)
                    acc[i][j] += a[i] * b[j];
        }
        __syncthreads();
    }
#pragma unroll
    for (int i = 0; i < 4; i++)
#pragma unroll
        for (int j = 0; j < 4; j++)
            C[(size_t)(m0 + ty * 4 + i) * ldc + n0 + tx * 4 + j] = alpha * acc[i][j];
}

// ---------------------------------------------------------------------------
// Scores: S[b,h,i,j] = 0.125 * sum_d Q[b,i,h*64+d]*K[b,j,h*64+d], masked j<=i
// grid: (T/BN, T/BM, B*H)
// ---------------------------------------------------------------------------
__global__ void scores_kernel(const float* __restrict__ Q,
                              const float* __restrict__ Kt,
                              float* __restrict__ W) {
    const int z = blockIdx.z;
    const int b = z / H_, h = z % H_;
    const int m0 = blockIdx.y * BM, n0 = blockIdx.x * BN;
    const int tid = threadIdx.x;
    const int tx = tid % 16, ty = tid / 16;

    float* Cz = W + (size_t)z * T_ * T_;

    if (n0 > m0) {  // fully masked tile (all j > i): write zeros
#pragma unroll
        for (int i = 0; i < 4; i++)
#pragma unroll
            for (int j = 0; j < 4; j++)
                Cz[(size_t)(m0 + ty * 4 + i) * T_ + n0 + tx * 4 + j] = 0.0f;
        return;
    }

    const float* A = Q + (size_t)b * T_ * C_ + h * DH_;
    const float* Bm = Kt + (size_t)b * T_ * C_ + h * DH_;

    __shared__ float As[BKK][BM];
    __shared__ float Bs[BKK][BN];
    float acc[4][4] = {};

    const int e = tid * 4;
    const int r = e / BKK, kko = e % BKK;

    for (int k0 = 0; k0 < DH_; k0 += BKK) {
        float4 va = *(const float4*)&A[(size_t)(m0 + r) * C_ + k0 + kko];
        float4 vb = *(const float4*)&Bm[(size_t)(n0 + r) * C_ + k0 + kko];
        As[kko + 0][r] = va.x; As[kko + 1][r] = va.y;
        As[kko + 2][r] = va.z; As[kko + 3][r] = va.w;
        Bs[kko + 0][r] = vb.x; Bs[kko + 1][r] = vb.y;
        Bs[kko + 2][r] = vb.z; Bs[kko + 3][r] = vb.w;
        __syncthreads();
#pragma unroll
        for (int kk = 0; kk < BKK; kk++) {
            float4 af = *(const float4*)&As[kk][ty * 4];
            float4 bf = *(const float4*)&Bs[kk][tx * 4];
            float a[4] = {af.x, af.y, af.z, af.w};
            float b2[4] = {bf.x, bf.y, bf.z, bf.w};
#pragma unroll
            for (int i = 0; i < 4; i++)
#pragma unroll
                for (int j = 0; j < 4; j++)
                    acc[i][j] += a[i] * b2[j];
        }
        __syncthreads();
    }
#pragma unroll
    for (int i = 0; i < 4; i++) {
        const int gi = m0 + ty * 4 + i;
#pragma unroll
        for (int j = 0; j < 4; j++) {
            const int gj = n0 + tx * 4 + j;
            Cz[(size_t)gi * T_ + gj] = (gj <= gi) ? 0.125f * acc[i][j] : 0.0f;
        }
    }
}

// ---------------------------------------------------------------------------
// Causal softmax, one block per row. Row length up to 2048 fits in smem.
// Masked tail (j > i) already holds 0.0 from scores_kernel; leave it.
// ---------------------------------------------------------------------------
__global__ void softmax_kernel(float* __restrict__ W) {
    const int r = blockIdx.x;          // [0, B*H*T)
    const int i = r % T_;
    const int valid = i + 1;
    float* row = W + (size_t)r * T_;

    __shared__ float buf[T_];
    __shared__ float red[256];
    const int tid = threadIdx.x;

    float mx = -1e30f;
    for (int j = tid; j < valid; j += 256) {
        float v = row[j];
        buf[j] = v;
        mx = fmaxf(mx, v);
    }
    red[tid] = mx;
    __syncthreads();
    for (int s = 128; s > 0; s >>= 1) {
        if (tid < s) red[tid] = fmaxf(red[tid], red[tid + s]);
        __syncthreads();
    }
    mx = red[0];
    __syncthreads();

    float sm = 0.0f;
    for (int j = tid; j < valid; j += 256) {
        float ev = expf(buf[j] - mx);
        buf[j] = ev;
        sm += ev;
    }
    red[tid] = sm;
    __syncthreads();
    for (int s = 128; s > 0; s >>= 1) {
        if (tid < s) red[tid] += red[tid + s];
        __syncthreads();
    }
    const float inv = 1.0f / red[0];
    for (int j = tid; j < valid; j += 256) row[j] = buf[j] * inv;
}

// ---------------------------------------------------------------------------
// PV: att[b, i, h*64+d] = sum_j W[b,h,i,j] * V[b, j, h*64+d]
// NN GEMM per (b,h): M=T, N=DH, K=T. grid: (1, T/BM, B*H)
// ---------------------------------------------------------------------------
__global__ void pv_kernel(const float* __restrict__ W,
                          const float* __restrict__ V,
                          float* __restrict__ O) {
    const int z = blockIdx.z;
    const int b = z / H_, h = z % H_;
    const int m0 = blockIdx.y * BM;
    const int tid = threadIdx.x;
    const int tx = tid % 16, ty = tid / 16;

    const float* A = W + (size_t)z * T_ * T_;            // [T, T], lda = T
    const float* Bm = V + (size_t)b * T_ * C_ + h * DH_; // B[k][n] = Bm[k*C_ + n]

    __shared__ float As[BKK][BM];
    __shared__ float Bs[BKK][BN];
    float acc[4][4] = {};

    const int e = tid * 4;
    const int ra = e / BKK, kka = e % BKK;  // A load coords
    const int kb = e / BN, nb = e % BN;     // B load coords

    // Causal: W[m0.., j] is zero for j > m0+63 → only need K up to m0+64
    const int kmax = m0 + BM;

    for (int k0 = 0; k0 < kmax; k0 += BKK) {
        float4 va = *(const float4*)&A[(size_t)(m0 + ra) * T_ + k0 + kka];
        As[kka + 0][ra] = va.x; As[kka + 1][ra] = va.y;
        As[kka + 2][ra] = va.z; As[kka + 3][ra] = va.w;
        float4 vb = *(const float4*)&Bm[(size_t)(k0 + kb) * C_ + nb];
        *(float4*)&Bs[kb][nb] = vb;
        __syncthreads();
#pragma unroll
        for (int kk = 0; kk < BKK; kk++) {
            float4 af = *(const float4*)&As[kk][ty * 4];
            float4 bf = *(const float4*)&Bs[kk][tx * 4];
            float a[4] = {af.x, af.y, af.z, af.w};
            float b2[4] = {bf.x, bf.y, bf.z, bf.w};
#pragma unroll
            for (int i = 0; i < 4; i++)
#pragma unroll
                for (int j = 0; j < 4; j++)
                    acc[i][j] += a[i] * b2[j];
        }
        __syncthreads();
    }
#pragma unroll
    for (int i = 0; i < 4; i++)
#pragma unroll
        for (int j = 0; j < 4; j++)
            O[(size_t)(b * T_ + m0 + ty * 4 + i) * C_ + h * DH_ + tx * 4 + j] = acc[i][j];
}

// ---------------------------------------------------------------------------
extern "C" void kernel_launch(void* const* d_in, const int* in_sizes, int n_in,
                              void* d_out, int out_size) {
    const float* x   = (const float*)d_in[0];
    const float* w_q = (const float*)d_in[1];
    const float* w_k = (const float*)d_in[2];
    const float* w_v = (const float*)d_in[3];
    const float* w_o = (const float*)d_in[4];

    float* qp; cudaGetSymbolAddress((void**)&qp, g_q);
    float* kp; cudaGetSymbolAddress((void**)&kp, g_k);
    float* vp; cudaGetSymbolAddress((void**)&vp, g_v);
    float* ap; cudaGetSymbolAddress((void**)&ap, g_att);

    float* final_out = (float*)d_out;                          // [B,T,C]
    float* w_out = (float*)d_out + (size_t)B_ * T_ * C_;       // [B,H,T,T]

    const dim3 blk(256);
    const dim3 gproj(C_ / BN, (B_ * T_) / BM);                 // (12, 64)

    // Projections: Q/K/V = x @ W^T
    gemm_nt_kernel<<<gproj, blk>>>(x, w_q, qp, C_, C_, C_, C_, 1.0f);
    gemm_nt_kernel<<<gproj, blk>>>(x, w_k, kp, C_, C_, C_, C_, 1.0f);
    gemm_nt_kernel<<<gproj, blk>>>(x, w_v, vp, C_, C_, C_, C_, 1.0f);

    // Scores with causal mask + scale
    scores_kernel<<<dim3(T_ / BN, T_ / BM, B_ * H_), blk>>>(qp, kp, w_out);

    // Softmax (writes normalized weights = second output)
    softmax_kernel<<<B_ * H_ * T_, blk>>>(w_out);

    // PV
    pv_kernel<<<dim3(1, T_ / BM, B_ * H_), blk>>>(w_out, vp, ap);

    // Final projection
    gemm_nt_kernel<<<gproj, blk>>>(ap, w_o, final_out, C_, C_, C_, C_, 1.0f);
}

// round 2
// speedup vs baseline: 1.2005x; 1.2005x over previous
#include <cuda_runtime.h>
#include <math.h>
#include <stdint.h>

#define B_   2
#define T_   2048
#define C_   768
#define H_   12
#define DH_  64
#define LOG2E 1.4426950408889634f
#define SK   20   // smem k-stride (padded 16 -> 20 for conflict-free frag gathers)

// Scratch (device globals — no allocation allowed)
__device__ float g_q[B_ * T_ * C_];
__device__ float g_k[B_ * T_ * C_];
__device__ float g_v[B_ * T_ * C_];
__device__ float g_att[B_ * T_ * C_];

// ---------------------------------------------------------------------------
// tf32 helpers
// ---------------------------------------------------------------------------
__device__ __forceinline__ uint32_t f2tf(float v) {
    uint32_t r;
    asm("cvt.rna.tf32.f32 %0, %1;" : "=r"(r) : "f"(v));
    return r;
}

__device__ __forceinline__ void mma8(float4& d, const uint32_t* a, const uint32_t* b) {
    asm("mma.sync.aligned.m16n8k8.row.col.f32.tf32.tf32.f32 "
        "{%0,%1,%2,%3}, {%4,%5,%6,%7}, {%8,%9}, {%0,%1,%2,%3};"
        : "+f"(d.x), "+f"(d.y), "+f"(d.z), "+f"(d.w)
        : "r"(a[0]), "r"(a[1]), "r"(a[2]), "r"(a[3]), "r"(b[0]), "r"(b[1]));
}

// Load a [128 rows x 16 k] fp32 tile (row stride ld) into hi/lo tf32 smem.
__device__ __forceinline__ void load_tile128(const float* __restrict__ src, int ld,
                                             uint32_t (*Sh)[SK], uint32_t (*Sl)[SK],
                                             int tid) {
#pragma unroll
    for (int it = 0; it < 2; it++) {
        int idx = tid + it * 256;            // 512 float4s total
        int row = idx >> 2;
        int ko  = (idx & 3) << 2;
        float4 v = *(const float4*)(src + (size_t)row * ld + ko);
        uint32_t h;
        h = f2tf(v.x); Sh[row][ko + 0] = h; Sl[row][ko + 0] = f2tf(v.x - __uint_as_float(h));
        h = f2tf(v.y); Sh[row][ko + 1] = h; Sl[row][ko + 1] = f2tf(v.y - __uint_as_float(h));
        h = f2tf(v.z); Sh[row][ko + 2] = h; Sl[row][ko + 2] = f2tf(v.z - __uint_as_float(h));
        h = f2tf(v.w); Sh[row][ko + 3] = h; Sl[row][ko + 3] = f2tf(v.w - __uint_as_float(h));
    }
}

// ---------------------------------------------------------------------------
// Generic NT GEMM via 3xTF32 tensor cores.
// C[m,n] = alpha * sum_k A[m*lda+k]*B[n*ldb+k].  M%128==0, N%128==0, K%16==0.
// ---------------------------------------------------------------------------
__global__ void __launch_bounds__(256) gemm_nt_tc(const float* __restrict__ A,
                                                  const float* __restrict__ Bm,
                                                  float* __restrict__ C,
                                                  int K, int lda, int ldb, int ldc,
                                                  float alpha) {
    __shared__ uint32_t Ah[128][SK], Al[128][SK], Bh[128][SK], Bl[128][SK];
    const int tid = threadIdx.x;
    const int m0 = blockIdx.y * 128, n0 = blockIdx.x * 128;
    const int warp = tid >> 5, lane = tid & 31;
    const int wm = (warp >> 2) * 64, wn = (warp & 3) * 32;
    const int r = lane >> 2, c = lane & 3;

    float4 acc[4][4];
#pragma unroll
    for (int i = 0; i < 4; i++)
#pragma unroll
        for (int j = 0; j < 4; j++) acc[i][j] = make_float4(0, 0, 0, 0);

    for (int k0 = 0; k0 < K; k0 += 16) {
        __syncthreads();
        load_tile128(A + (size_t)m0 * lda + k0, lda, Ah, Al, tid);
        load_tile128(Bm + (size_t)n0 * ldb + k0, ldb, Bh, Bl, tid);
        __syncthreads();
#pragma unroll
        for (int kb = 0; kb < 16; kb += 8) {
            uint32_t bh[4][2], bl[4][2];
#pragma unroll
            for (int nj = 0; nj < 4; nj++) {
                int col = wn + nj * 8 + r;
                bh[nj][0] = Bh[col][kb + c]; bh[nj][1] = Bh[col][kb + c + 4];
                bl[nj][0] = Bl[col][kb + c]; bl[nj][1] = Bl[col][kb + c + 4];
            }
#pragma unroll
            for (int mi = 0; mi < 4; mi++) {
                int row = wm + mi * 16 + r;
                uint32_t ah[4], al[4];
                ah[0] = Ah[row][kb + c];     ah[1] = Ah[row + 8][kb + c];
                ah[2] = Ah[row][kb + c + 4]; ah[3] = Ah[row + 8][kb + c + 4];
                al[0] = Al[row][kb + c];     al[1] = Al[row + 8][kb + c];
                al[2] = Al[row][kb + c + 4]; al[3] = Al[row + 8][kb + c + 4];
#pragma unroll
                for (int nj = 0; nj < 4; nj++) {
                    mma8(acc[mi][nj], al, bh[nj]);
                    mma8(acc[mi][nj], ah, bl[nj]);
                    mma8(acc[mi][nj], ah, bh[nj]);
                }
            }
        }
    }
#pragma unroll
    for (int mi = 0; mi < 4; mi++)
#pragma unroll
        for (int nj = 0; nj < 4; nj++) {
            int gm = m0 + wm + mi * 16 + r;
            int gn = n0 + wn + nj * 8 + 2 * c;
            float2 v0 = make_float2(alpha * acc[mi][nj].x, alpha * acc[mi][nj].y);
            float2 v1 = make_float2(alpha * acc[mi][nj].z, alpha * acc[mi][nj].w);
            *(float2*)&C[(size_t)gm * ldc + gn]       = v0;
            *(float2*)&C[(size_t)(gm + 8) * ldc + gn] = v1;
        }
}

// ---------------------------------------------------------------------------
// Scores: S[z,i,j] = 0.125 * Q[b,i,h,:] . K[b,j,h,:], causal-masked.
// grid (16, 16, 24)
// ---------------------------------------------------------------------------
__global__ void __launch_bounds__(256) scores_tc(const float* __restrict__ Q,
                                                 const float* __restrict__ Kt,
                                                 float* __restrict__ W) {
    const int z = blockIdx.z;
    const int b = z / H_, h = z % H_;
    const int m0 = blockIdx.y * 128, n0 = blockIdx.x * 128;
    const int tid = threadIdx.x;
    float* Cz = W + (size_t)z * T_ * T_;

    if (n0 > m0) {  // fully masked tile -> zeros (float4 stores)
        const float4 zz = make_float4(0, 0, 0, 0);
        for (int idx = tid; idx < 128 * 32; idx += 256) {
            int row = idx >> 5, c4 = (idx & 31) << 2;
            *(float4*)&Cz[(size_t)(m0 + row) * T_ + n0 + c4] = zz;
        }
        return;
    }

    __shared__ uint32_t Ah[128][SK], Al[128][SK], Bh[128][SK], Bl[128][SK];
    const int warp = tid >> 5, lane = tid & 31;
    const int wm = (warp >> 2) * 64, wn = (warp & 3) * 32;
    const int r = lane >> 2, c = lane & 3;
    const float* Ap = Q + (size_t)b * T_ * C_ + h * DH_;
    const float* Bp = Kt + (size_t)b * T_ * C_ + h * DH_;

    float4 acc[4][4];
#pragma unroll
    for (int i = 0; i < 4; i++)
#pragma unroll
        for (int j = 0; j < 4; j++) acc[i][j] = make_float4(0, 0, 0, 0);

    for (int k0 = 0; k0 < DH_; k0 += 16) {
        __syncthreads();
        load_tile128(Ap + (size_t)m0 * C_ + k0, C_, Ah, Al, tid);
        load_tile128(Bp + (size_t)n0 * C_ + k0, C_, Bh, Bl, tid);
        __syncthreads();
#pragma unroll
        for (int kb = 0; kb < 16; kb += 8) {
            uint32_t bh[4][2], bl[4][2];
#pragma unroll
            for (int nj = 0; nj < 4; nj++) {
                int col = wn + nj * 8 + r;
                bh[nj][0] = Bh[col][kb + c]; bh[nj][1] = Bh[col][kb + c + 4];
                bl[nj][0] = Bl[col][kb + c]; bl[nj][1] = Bl[col][kb + c + 4];
            }
#pragma unroll
            for (int mi = 0; mi < 4; mi++) {
                int row = wm + mi * 16 + r;
                uint32_t ah[4], al[4];
                ah[0] = Ah[row][kb + c];     ah[1] = Ah[row + 8][kb + c];
                ah[2] = Ah[row][kb + c + 4]; ah[3] = Ah[row + 8][kb + c + 4];
                al[0] = Al[row][kb + c];     al[1] = Al[row + 8][kb + c];
                al[2] = Al[row][kb + c + 4]; al[3] = Al[row + 8][kb + c + 4];
#pragma unroll
                for (int nj = 0; nj < 4; nj++) {
                    mma8(acc[mi][nj], al, bh[nj]);
                    mma8(acc[mi][nj], ah, bl[nj]);
                    mma8(acc[mi][nj], ah, bh[nj]);
                }
            }
        }
    }

    const bool diag = (n0 == m0);
#pragma unroll
    for (int mi = 0; mi < 4; mi++)
#pragma unroll
        for (int nj = 0; nj < 4; nj++) {
            int gm = m0 + wm + mi * 16 + r;
            int gn = n0 + wn + nj * 8 + 2 * c;
            float x0 = 0.125f * acc[mi][nj].x, y0 = 0.125f * acc[mi][nj].y;
            float z1 = 0.125f * acc[mi][nj].z, w1 = 0.125f * acc[mi][nj].w;
            if (diag) {
                if (gn > gm) x0 = 0.0f;
                if (gn + 1 > gm) y0 = 0.0f;
                if (gn > gm + 8) z1 = 0.0f;
                if (gn + 1 > gm + 8) w1 = 0.0f;
            }
            *(float2*)&Cz[(size_t)gm * T_ + gn]       = make_float2(x0, y0);
            *(float2*)&Cz[(size_t)(gm + 8) * T_ + gn] = make_float2(z1, w1);
        }
}

// ---------------------------------------------------------------------------
// Causal softmax, one block per row (valid prefix only).
// ---------------------------------------------------------------------------
__global__ void __launch_bounds__(256) softmax_kernel(float* __restrict__ W) {
    const int rrow = blockIdx.x;          // [0, B*H*T)
    const int i = rrow % T_;
    const int valid = i + 1;
    float* row = W + (size_t)rrow * T_;

    __shared__ float buf[T_];
    __shared__ float warpred[8];
    const int tid = threadIdx.x;

    float mx = -1e30f;
    for (int j = tid; j < valid; j += 256) {
        float v = row[j];
        buf[j] = v;
        mx = fmaxf(mx, v);
    }
#pragma unroll
    for (int o = 16; o; o >>= 1) mx = fmaxf(mx, __shfl_xor_sync(0xffffffffu, mx, o));
    if ((tid & 31) == 0) warpred[tid >> 5] = mx;
    __syncthreads();
    mx = warpred[0];
#pragma unroll
    for (int w = 1; w < 8; w++) mx = fmaxf(mx, warpred[w]);

    float sm = 0.0f;
    for (int j = tid; j < valid; j += 256) {
        float ev = exp2f((buf[j] - mx) * LOG2E);
        buf[j] = ev;
        sm += ev;
    }
#pragma unroll
    for (int o = 16; o; o >>= 1) sm += __shfl_xor_sync(0xffffffffu, sm, o);
    __syncthreads();
    if ((tid & 31) == 0) warpred[tid >> 5] = sm;
    __syncthreads();
    sm = 0.0f;
#pragma unroll
    for (int w = 0; w < 8; w++) sm += warpred[w];
    const float inv = 1.0f / sm;
    for (int j = tid; j < valid; j += 256) row[j] = buf[j] * inv;
}

// ---------------------------------------------------------------------------
// PV: O[b,i,h*64+d] = sum_j W[z,i,j] * V[b,j,h*64+d]   (NN GEMM, N=64)
// grid (1, 16, 24); K clipped at m0+128 (causal zeros beyond).
// ---------------------------------------------------------------------------
__global__ void __launch_bounds__(256) pv_tc(const float* __restrict__ W,
                                             const float* __restrict__ V,
                                             float* __restrict__ O) {
    const int z = blockIdx.z;
    const int b = z / H_, h = z % H_;
    const int m0 = blockIdx.y * 128;
    const int tid = threadIdx.x;
    const int warp = tid >> 5, lane = tid & 31;
    const int wm = (warp >> 2) * 64, wn = (warp & 3) * 16;
    const int r = lane >> 2, c = lane & 3;

    const float* Ap = W + (size_t)z * T_ * T_;             // [T,T] row-major
    const float* Vp = V + (size_t)b * T_ * C_ + h * DH_;   // V[k][n], stride C_

    __shared__ uint32_t Ah[128][SK], Al[128][SK], Bh[64][SK], Bl[64][SK];

    float4 acc[4][2];
#pragma unroll
    for (int i = 0; i < 4; i++)
#pragma unroll
        for (int j = 0; j < 2; j++) acc[i][j] = make_float4(0, 0, 0, 0);

    const int kmax = m0 + 128;
    for (int k0 = 0; k0 < kmax; k0 += 16) {
        __syncthreads();
        load_tile128(Ap + (size_t)m0 * T_ + k0, T_, Ah, Al, tid);
        {   // B tile: Bs[n][k] = V[k0+k][n], 64n x 16k, one float4 per thread
            int kr = tid >> 4;            // 0..15
            int nc = (tid & 15) << 2;     // 0..60
            float4 v = *(const float4*)(Vp + (size_t)(k0 + kr) * C_ + nc);
            uint32_t hh;
            hh = f2tf(v.x); Bh[nc + 0][kr] = hh; Bl[nc + 0][kr] = f2tf(v.x - __uint_as_float(hh));
            hh = f2tf(v.y); Bh[nc + 1][kr] = hh; Bl[nc + 1][kr] = f2tf(v.y - __uint_as_float(hh));
            hh = f2tf(v.z); Bh[nc + 2][kr] = hh; Bl[nc + 2][kr] = f2tf(v.z - __uint_as_float(hh));
            hh = f2tf(v.w); Bh[nc + 3][kr] = hh; Bl[nc + 3][kr] = f2tf(v.w - __uint_as_float(hh));
        }
        __syncthreads();
#pragma unroll
        for (int kb = 0; kb < 16; kb += 8) {
            uint32_t bh[2][2], bl[2][2];
#pragma unroll
            for (int nj = 0; nj < 2; nj++) {
                int col = wn + nj * 8 + r;
                bh[nj][0] = Bh[col][kb + c]; bh[nj][1] = Bh[col][kb + c + 4];
                bl[nj][0] = Bl[col][kb + c]; bl[nj][1] = Bl[col][kb + c + 4];
            }
#pragma unroll
            for (int mi = 0; mi < 4; mi++) {
                int row = wm + mi * 16 + r;
                uint32_t ah[4], al[4];
                ah[0] = Ah[row][kb + c];     ah[1] = Ah[row + 8][kb + c];
                ah[2] = Ah[row][kb + c + 4]; ah[3] = Ah[row + 8][kb + c + 4];
                al[0] = Al[row][kb + c];     al[1] = Al[row + 8][kb + c];
                al[2] = Al[row][kb + c + 4]; al[3] = Al[row + 8][kb + c + 4];
#pragma unroll
                for (int nj = 0; nj < 2; nj++) {
                    mma8(acc[mi][nj], al, bh[nj]);
                    mma8(acc[mi][nj], ah, bl[nj]);
                    mma8(acc[mi][nj], ah, bh[nj]);
                }
            }
        }
    }
#pragma unroll
    for (int mi = 0; mi < 4; mi++)
#pragma unroll
        for (int nj = 0; nj < 2; nj++) {
            int gm = m0 + wm + mi * 16 + r;
            int gn = wn + nj * 8 + 2 * c;
            *(float2*)&O[(size_t)(b * T_ + gm) * C_ + h * DH_ + gn] =
                make_float2(acc[mi][nj].x, acc[mi][nj].y);
            *(float2*)&O[(size_t)(b * T_ + gm + 8) * C_ + h * DH_ + gn] =
                make_float2(acc[mi][nj].z, acc[mi][nj].w);
        }
}

// ---------------------------------------------------------------------------
extern "C" void kernel_launch(void* const* d_in, const int* in_sizes, int n_in,
                              void* d_out, int out_size) {
    const float* x   = (const float*)d_in[0];
    const float* w_q = (const float*)d_in[1];
    const float* w_k = (const float*)d_in[2];
    const float* w_v = (const float*)d_in[3];
    const float* w_o = (const float*)d_in[4];

    float* qp; cudaGetSymbolAddress((void**)&qp, g_q);
    float* kp; cudaGetSymbolAddress((void**)&kp, g_k);
    float* vp; cudaGetSymbolAddress((void**)&vp, g_v);
    float* ap; cudaGetSymbolAddress((void**)&ap, g_att);

    float* final_out = (float*)d_out;                       // [B,T,C]
    float* w_out = (float*)d_out + (size_t)B_ * T_ * C_;    // [B,H,T,T]

    const dim3 blk(256);
    const dim3 gproj(C_ / 128, (B_ * T_) / 128);            // (6, 32)

    gemm_nt_tc<<<gproj, blk>>>(x, w_q, qp, C_, C_, C_, C_, 1.0f);
    gemm_nt_tc<<<gproj, blk>>>(x, w_k, kp, C_, C_, C_, C_, 1.0f);
    gemm_nt_tc<<<gproj, blk>>>(x, w_v, vp, C_, C_, C_, C_, 1.0f);

    scores_tc<<<dim3(T_ / 128, T_ / 128, B_ * H_), blk>>>(qp, kp, w_out);

    softmax_kernel<<<B_ * H_ * T_, blk>>>(w_out);

    pv_tc<<<dim3(1, T_ / 128, B_ * H_), blk>>>(w_out, vp, ap);

    gemm_nt_tc<<<gproj, blk>>>(ap, w_o, final_out, C_, C_, C_, C_, 1.0f);
}